// round 3
// baseline (speedup 1.0000x reference)
#include <cuda_runtime.h>

// EM_fusion: softmax over [x, x] == [0.5, 0.5] exactly, so the reference
// collapses to fused = 0.5*(f1 + f2). Pure HBM-bound streaming mean.
// n = 131072*768 = 100663296 floats; n4 = 25165824 float4s, divisible by 512,
// so 2 float4 per thread with 256-thread blocks gives an exact grid (49152).
//
// vs R1 (165.9us kernel, DRAM 85.9%, 7025 GB/s):
//  - 2x float4 per thread -> 4 front-batched independent 16B loads (MLP_p1=4)
//  - __ldcs on loads (read-once, evict-first: keep L2 ways for write stream)
//  - __stcs on stores (write-once, never re-read)

#define THREADS 256

__global__ __launch_bounds__(THREADS)
void em_fusion_mean_kernel(const float4* __restrict__ a,
                           const float4* __restrict__ b,
                           float4* __restrict__ out,
                           int n4) {
    int i = 2 * (blockIdx.x * THREADS) + threadIdx.x;

    if (i + THREADS < n4) {
        // Front-batch all four independent loads, then compute, then store.
        float4 va0 = __ldcs(&a[i]);
        float4 vb0 = __ldcs(&b[i]);
        float4 va1 = __ldcs(&a[i + THREADS]);
        float4 vb1 = __ldcs(&b[i + THREADS]);

        float4 vo0, vo1;
        vo0.x = 0.5f * (va0.x + vb0.x);
        vo0.y = 0.5f * (va0.y + vb0.y);
        vo0.z = 0.5f * (va0.z + vb0.z);
        vo0.w = 0.5f * (va0.w + vb0.w);
        vo1.x = 0.5f * (va1.x + vb1.x);
        vo1.y = 0.5f * (va1.y + vb1.y);
        vo1.z = 0.5f * (va1.z + vb1.z);
        vo1.w = 0.5f * (va1.w + vb1.w);

        __stcs(&out[i], vo0);
        __stcs(&out[i + THREADS], vo1);
    } else {
        // Ragged edge (not hit for this shape, kept for generality).
        for (int j = i; j < n4; j += THREADS) {
            float4 va = __ldcs(&a[j]);
            float4 vb = __ldcs(&b[j]);
            float4 vo;
            vo.x = 0.5f * (va.x + vb.x);
            vo.y = 0.5f * (va.y + vb.y);
            vo.z = 0.5f * (va.z + vb.z);
            vo.w = 0.5f * (va.w + vb.w);
            __stcs(&out[j], vo);
        }
    }
}

// Scalar tail if n % 4 != 0 (not hit for this shape).
__global__ void em_fusion_tail_kernel(const float* __restrict__ a,
                                      const float* __restrict__ b,
                                      float* __restrict__ out,
                                      int start, int n) {
    int i = start + blockIdx.x * blockDim.x + threadIdx.x;
    if (i < n) {
        out[i] = 0.5f * (a[i] + b[i]);
    }
}

extern "C" void kernel_launch(void* const* d_in, const int* in_sizes, int n_in,
                              void* d_out, int out_size) {
    const float* f1 = (const float*)d_in[0];
    const float* f2 = (const float*)d_in[1];
    float* out = (float*)d_out;

    int n = in_sizes[0];          // 100663296
    int n4 = n >> 2;              // 25165824
    int tail_start = n4 << 2;

    const int elems_per_block = THREADS * 2;
    int blocks = (n4 + elems_per_block - 1) / elems_per_block;  // 49152 exact
    em_fusion_mean_kernel<<<blocks, THREADS>>>(
        (const float4*)f1, (const float4*)f2, (float4*)out, n4);

    int tail = n - tail_start;
    if (tail > 0) {
        em_fusion_tail_kernel<<<1, 128>>>(f1, f2, out, tail_start, n);
    }
}

// round 4
// speedup vs baseline: 1.0124x; 1.0124x over previous
#include <cuda_runtime.h>

// EM_fusion: softmax over [x, x] == [0.5, 0.5] exactly, so the reference
// collapses to fused = 0.5*(f1 + f2). Pure HBM-bound streaming mean.
// n = 131072*768 = 100663296 floats (divisible by 4).
//
// R4 = R1 structure (best: 165.9us kernel, DRAM 85.9%, 7025 GB/s, 18 regs)
// with ONE controlled change: __ldcs evict-first loads instead of __ldg.
// R3's MLP-4 blocking regressed (167.7us, 32 regs, issue 8.2%) -> reverted.

#define THREADS 256

__global__ __launch_bounds__(THREADS)
void em_fusion_mean_kernel(const float4* __restrict__ a,
                           const float4* __restrict__ b,
                           float4* __restrict__ out,
                           int n4) {
    int i = blockIdx.x * THREADS + threadIdx.x;
    if (i < n4) {
        float4 va = __ldcs(&a[i]);   // read-once: evict-first
        float4 vb = __ldcs(&b[i]);
        float4 vo;
        vo.x = 0.5f * (va.x + vb.x);
        vo.y = 0.5f * (va.y + vb.y);
        vo.z = 0.5f * (va.z + vb.z);
        vo.w = 0.5f * (va.w + vb.w);
        __stcs(&out[i], vo);         // write-once, never re-read
    }
}

// Scalar tail if n % 4 != 0 (not hit for this shape).
__global__ void em_fusion_tail_kernel(const float* __restrict__ a,
                                      const float* __restrict__ b,
                                      float* __restrict__ out,
                                      int start, int n) {
    int i = start + blockIdx.x * blockDim.x + threadIdx.x;
    if (i < n) {
        out[i] = 0.5f * (a[i] + b[i]);
    }
}

extern "C" void kernel_launch(void* const* d_in, const int* in_sizes, int n_in,
                              void* d_out, int out_size) {
    const float* f1 = (const float*)d_in[0];
    const float* f2 = (const float*)d_in[1];
    float* out = (float*)d_out;

    int n = in_sizes[0];          // 100663296
    int n4 = n >> 2;              // 25165824
    int tail_start = n4 << 2;

    int blocks = (n4 + THREADS - 1) / THREADS;  // 98304 exact
    em_fusion_mean_kernel<<<blocks, THREADS>>>(
        (const float4*)f1, (const float4*)f2, (float4*)out, n4);

    int tail = n - tail_start;
    if (tail > 0) {
        em_fusion_tail_kernel<<<1, 128>>>(f1, f2, out, tail_start, n);
    }
}

// round 6
// speedup vs baseline: 1.0329x; 1.0202x over previous
#include <cuda_runtime.h>

// EM_fusion: softmax over [x, x] == [0.5, 0.5] exactly, so the reference
// collapses to fused = 0.5*(f1 + f2). Pure HBM-bound streaming mean.
// n = 131072*768 = 100663296 floats (divisible by 4).
//
// R6 = resubmit of R5 (infra failure, no signal):
// R4 best (175.7us total, 166.3us kernel, DRAM 86.0%, 7036 GB/s) with ONE
// controlled change: 512-thread blocks (49152 blocks) for larger contiguous
// per-CTA footprint / fewer CTA launches. Everything else identical.

#define THREADS 512

__global__ __launch_bounds__(THREADS)
void em_fusion_mean_kernel(const float4* __restrict__ a,
                           const float4* __restrict__ b,
                           float4* __restrict__ out,
                           int n4) {
    int i = blockIdx.x * THREADS + threadIdx.x;
    if (i < n4) {
        float4 va = __ldcs(&a[i]);   // read-once: evict-first
        float4 vb = __ldcs(&b[i]);
        float4 vo;
        vo.x = 0.5f * (va.x + vb.x);
        vo.y = 0.5f * (va.y + vb.y);
        vo.z = 0.5f * (va.z + vb.z);
        vo.w = 0.5f * (va.w + vb.w);
        __stcs(&out[i], vo);         // write-once, never re-read
    }
}

// Scalar tail if n % 4 != 0 (not hit for this shape).
__global__ void em_fusion_tail_kernel(const float* __restrict__ a,
                                      const float* __restrict__ b,
                                      float* __restrict__ out,
                                      int start, int n) {
    int i = start + blockIdx.x * blockDim.x + threadIdx.x;
    if (i < n) {
        out[i] = 0.5f * (a[i] + b[i]);
    }
}

extern "C" void kernel_launch(void* const* d_in, const int* in_sizes, int n_in,
                              void* d_out, int out_size) {
    const float* f1 = (const float*)d_in[0];
    const float* f2 = (const float*)d_in[1];
    float* out = (float*)d_out;

    int n = in_sizes[0];          // 100663296
    int n4 = n >> 2;              // 25165824
    int tail_start = n4 << 2;

    int blocks = (n4 + THREADS - 1) / THREADS;  // 49152 exact
    em_fusion_mean_kernel<<<blocks, THREADS>>>(
        (const float4*)f1, (const float4*)f2, (float4*)out, n4);

    int tail = n - tail_start;
    if (tail > 0) {
        em_fusion_tail_kernel<<<1, 128>>>(f1, f2, out, tail_start, n);
    }
}